// round 1
// baseline (speedup 1.0000x reference)
#include <cuda_runtime.h>

#define N_ATOMS 4096
#define N_PAIRS 4000000
#define CUTOFF 12.0f
#define R_REP 16
#define PAIR_BLOCKS 1184
#define PAIR_THREADS 256

// Replicated force accumulators: R_REP copies of [N_ATOMS][4] floats (~1 MB, L2-resident).
__device__ float g_scratch[R_REP * N_ATOMS * 4];

__global__ void zero_kernel(float* d_out, int out_size) {
    int tid = blockIdx.x * blockDim.x + threadIdx.x;
    int stride = gridDim.x * blockDim.x;
    const int total = R_REP * N_ATOMS * 4;
    for (int j = tid; j < total; j += stride) g_scratch[j] = 0.0f;
    for (int j = tid; j < out_size; j += stride) d_out[j] = 0.0f;
}

__global__ void __launch_bounds__(PAIR_THREADS) pair_kernel(
    const float* __restrict__ dist_mat,
    const float* __restrict__ vector_mat,
    const float* __restrict__ bcoef,
    const int2*  __restrict__ coord_idx,
    float* __restrict__ d_out)
{
    int tid = blockIdx.x * blockDim.x + threadIdx.x;
    int stride = gridDim.x * blockDim.x;
    float* rep = g_scratch + (size_t)(blockIdx.x % R_REP) * (N_ATOMS * 4);

    float esum = 0.0f;

    for (int i = tid; i < N_PAIRS; i += stride) {
        int2 ab = __ldg(&coord_idx[i]);
        long ofs = (long)ab.x * N_ATOMS + ab.y;
        float d = __ldg(&dist_mat[ofs]);
        if (d <= CUTOFF) {
            float B = __ldg(&bcoef[i]);
            float invd = 1.0f / d;               // IEEE divide (no fast-math flags assumed)
            float inv2 = invd * invd;
            float inv6 = inv2 * inv2 * inv2;
            float e = B * inv6;
            esum += e;
            float f = -6.0f * e * invd;          // -6 * B * invd^7

            const float* v = vector_mat + ofs * 3;
            float vx = __ldg(v + 0);
            float vy = __ldg(v + 1);
            float vz = __ldg(v + 2);
            float fx = f * vx, fy = f * vy, fz = f * vz;

            float* pa = rep + ab.x * 4;
            float* pb = rep + ab.y * 4;
            asm volatile("red.global.add.v4.f32 [%0], {%1,%2,%3,%4};"
                         :: "l"(pa), "f"(fx), "f"(fy), "f"(fz), "f"(0.0f) : "memory");
            asm volatile("red.global.add.v4.f32 [%0], {%1,%2,%3,%4};"
                         :: "l"(pb), "f"(-fx), "f"(-fy), "f"(-fz), "f"(0.0f) : "memory");
        }
    }

    // Energy: warp reduce -> block reduce -> one atomic per block.
    #pragma unroll
    for (int o = 16; o > 0; o >>= 1)
        esum += __shfl_xor_sync(0xffffffffu, esum, o);

    __shared__ float warp_s[PAIR_THREADS / 32];
    int lane = threadIdx.x & 31;
    int wid  = threadIdx.x >> 5;
    if (lane == 0) warp_s[wid] = esum;
    __syncthreads();
    if (wid == 0) {
        float v = (lane < (PAIR_THREADS / 32)) ? warp_s[lane] : 0.0f;
        #pragma unroll
        for (int o = 16; o > 0; o >>= 1)
            v += __shfl_xor_sync(0xffffffffu, v, o);
        if (lane == 0) atomicAdd(d_out, v);
    }
}

__global__ void reduce_kernel(const float* __restrict__ forces_in, float* __restrict__ d_out) {
    int a = blockIdx.x * blockDim.x + threadIdx.x;
    if (a < N_ATOMS) {
        float fx = 0.0f, fy = 0.0f, fz = 0.0f;
        #pragma unroll
        for (int r = 0; r < R_REP; r++) {
            const float4 v = *reinterpret_cast<const float4*>(
                g_scratch + (size_t)r * N_ATOMS * 4 + a * 4);
            fx += v.x; fy += v.y; fz += v.z;
        }
        d_out[1 + a * 3 + 0] = forces_in[a * 3 + 0] + fx;
        d_out[1 + a * 3 + 1] = forces_in[a * 3 + 1] + fy;
        d_out[1 + a * 3 + 2] = forces_in[a * 3 + 2] + fz;
    }
}

extern "C" void kernel_launch(void* const* d_in, const int* in_sizes, int n_in,
                              void* d_out, int out_size) {
    const float* dist_mat   = (const float*)d_in[0];   // (4096, 4096) f32
    const float* vector_mat = (const float*)d_in[1];   // (4096, 4096, 3) f32
    const float* forces_in  = (const float*)d_in[2];   // (4096, 3) f32 zeros
    const float* bcoef      = (const float*)d_in[3];   // (N_PAIRS,) f32
    const int2*  coord_idx  = (const int2*)d_in[4];    // (N_PAIRS, 2) i32

    float* out = (float*)d_out;                        // [energy, forces(4096*3)]

    zero_kernel<<<256, 256>>>(out, out_size);
    pair_kernel<<<PAIR_BLOCKS, PAIR_THREADS>>>(dist_mat, vector_mat, bcoef, coord_idx, out);
    reduce_kernel<<<(N_ATOMS + 255) / 256, 256>>>(forces_in, out);
}

// round 2
// speedup vs baseline: 1.0038x; 1.0038x over previous
#include <cuda_runtime.h>

#define N_ATOMS 4096
#define N_PAIRS 4000000
#define CUTOFF 12.0f
#define R_REP 16
#define PAIR_BLOCKS 1184
#define PAIR_THREADS 256
#define N_QUADS (N_PAIRS / 4)

// Replicated force accumulators: R_REP copies of [N_ATOMS][4] floats (~1 MB, L2-resident).
__device__ float g_scratch[R_REP * N_ATOMS * 4];

__global__ void zero_kernel(float* d_out, int out_size) {
    int tid = blockIdx.x * blockDim.x + threadIdx.x;
    int stride = gridDim.x * blockDim.x;
    const int total = R_REP * N_ATOMS * 4;
    for (int j = tid; j < total; j += stride) g_scratch[j] = 0.0f;
    for (int j = tid; j < out_size; j += stride) d_out[j] = 0.0f;
}

__device__ __forceinline__ void do_pair(float d, float B, long ofs,
                                        const float* __restrict__ vector_mat,
                                        float* __restrict__ rep,
                                        int a, int b, float& esum) {
    if (d <= CUTOFF) {
        float invd = 1.0f / d;
        float inv2 = invd * invd;
        float inv6 = inv2 * inv2 * inv2;
        float e = B * inv6;
        esum += e;
        float f = -6.0f * e * invd;

        const float* v = vector_mat + ofs * 3;
        float vx = __ldg(v + 0);
        float vy = __ldg(v + 1);
        float vz = __ldg(v + 2);
        float fx = f * vx, fy = f * vy, fz = f * vz;

        float* pa = rep + a * 4;
        float* pb = rep + b * 4;
        asm volatile("red.global.add.v4.f32 [%0], {%1,%2,%3,%4};"
                     :: "l"(pa), "f"(fx), "f"(fy), "f"(fz), "f"(0.0f) : "memory");
        asm volatile("red.global.add.v4.f32 [%0], {%1,%2,%3,%4};"
                     :: "l"(pb), "f"(-fx), "f"(-fy), "f"(-fz), "f"(0.0f) : "memory");
    }
}

__global__ void __launch_bounds__(PAIR_THREADS) pair_kernel(
    const float* __restrict__ dist_mat,
    const float* __restrict__ vector_mat,
    const float* __restrict__ bcoef,
    const int4*  __restrict__ coord_idx4,   // 2 pairs per int4
    float* __restrict__ d_out)
{
    int tid = blockIdx.x * blockDim.x + threadIdx.x;
    int stride = gridDim.x * blockDim.x;
    float* rep = g_scratch + (size_t)(blockIdx.x % R_REP) * (N_ATOMS * 4);

    float esum = 0.0f;

    // 4 pairs per iteration: front-batched loads for MLP.
    for (int i = tid; i < N_QUADS; i += stride) {
        int4 c01 = __ldcs(&coord_idx4[2 * i + 0]);
        int4 c23 = __ldcs(&coord_idx4[2 * i + 1]);
        float4 B = __ldcs((const float4*)bcoef + i);

        long o0 = (long)c01.x * N_ATOMS + c01.y;
        long o1 = (long)c01.z * N_ATOMS + c01.w;
        long o2 = (long)c23.x * N_ATOMS + c23.y;
        long o3 = (long)c23.z * N_ATOMS + c23.w;

        float d0 = __ldg(&dist_mat[o0]);
        float d1 = __ldg(&dist_mat[o1]);
        float d2 = __ldg(&dist_mat[o2]);
        float d3 = __ldg(&dist_mat[o3]);

        do_pair(d0, B.x, o0, vector_mat, rep, c01.x, c01.y, esum);
        do_pair(d1, B.y, o1, vector_mat, rep, c01.z, c01.w, esum);
        do_pair(d2, B.z, o2, vector_mat, rep, c23.x, c23.y, esum);
        do_pair(d3, B.w, o3, vector_mat, rep, c23.z, c23.w, esum);
    }

    // Energy: warp reduce -> block reduce -> one atomic per block.
    #pragma unroll
    for (int o = 16; o > 0; o >>= 1)
        esum += __shfl_xor_sync(0xffffffffu, esum, o);

    __shared__ float warp_s[PAIR_THREADS / 32];
    int lane = threadIdx.x & 31;
    int wid  = threadIdx.x >> 5;
    if (lane == 0) warp_s[wid] = esum;
    __syncthreads();
    if (wid == 0) {
        float v = (lane < (PAIR_THREADS / 32)) ? warp_s[lane] : 0.0f;
        #pragma unroll
        for (int o = 16; o > 0; o >>= 1)
            v += __shfl_xor_sync(0xffffffffu, v, o);
        if (lane == 0) atomicAdd(d_out, v);
    }
}

__global__ void reduce_kernel(const float* __restrict__ forces_in, float* __restrict__ d_out) {
    int a = blockIdx.x * blockDim.x + threadIdx.x;
    if (a < N_ATOMS) {
        float fx = 0.0f, fy = 0.0f, fz = 0.0f;
        #pragma unroll
        for (int r = 0; r < R_REP; r++) {
            const float4 v = *reinterpret_cast<const float4*>(
                g_scratch + (size_t)r * N_ATOMS * 4 + a * 4);
            fx += v.x; fy += v.y; fz += v.z;
        }
        d_out[1 + a * 3 + 0] = forces_in[a * 3 + 0] + fx;
        d_out[1 + a * 3 + 1] = forces_in[a * 3 + 1] + fy;
        d_out[1 + a * 3 + 2] = forces_in[a * 3 + 2] + fz;
    }
}

extern "C" void kernel_launch(void* const* d_in, const int* in_sizes, int n_in,
                              void* d_out, int out_size) {
    const float* dist_mat   = (const float*)d_in[0];   // (4096, 4096) f32
    const float* vector_mat = (const float*)d_in[1];   // (4096, 4096, 3) f32
    const float* forces_in  = (const float*)d_in[2];   // (4096, 3) f32 zeros
    const float* bcoef      = (const float*)d_in[3];   // (N_PAIRS,) f32
    const int4*  coord_idx4 = (const int4*)d_in[4];    // (N_PAIRS, 2) i32, 2 pairs per int4

    float* out = (float*)d_out;                        // [energy, forces(4096*3)]

    zero_kernel<<<1024, 256>>>(out, out_size);
    pair_kernel<<<PAIR_BLOCKS, PAIR_THREADS>>>(dist_mat, vector_mat, bcoef, coord_idx4, out);
    reduce_kernel<<<(N_ATOMS + 255) / 256, 256>>>(forces_in, out);
}